// round 10
// baseline (speedup 1.0000x reference)
#include <cuda_runtime.h>
#include <cuda_bf16.h>

#define MAXN 100000
#define MAXE 1600000
#define INF_DIM 256     // IN = H*F = 256
#define HEADS 4

// Scratch (device globals; no allocation allowed)
__device__ float g_feat_src[(size_t)MAXN * INF_DIM];
__device__ float g_el[MAXN * HEADS];
__device__ float g_er[MAXN * HEADS];
__device__ float g_esum[MAXN * HEADS];
__device__ float g_ex[(size_t)MAXE * HEADS];   // fallback if 'a' not in d_out
__device__ int   g_is64;
// Pre-converted weights: [2][256 outcol][256 k] bf16 hi/lo
__device__ __nv_bfloat16 g_Bh[2 * 256 * 256];
__device__ __nv_bfloat16 g_Bl[2 * 256 * 256];
// CSR-by-dst scratch
__device__ int g_cnt[MAXN];
__device__ int g_off[MAXN];
__device__ int g_cur[MAXN];
__device__ int g_csr[MAXE];       // edge id grouped by dst
__device__ int g_part[128];

// Side stream + events (module-load init; proven harness-safe).
static cudaStream_t g_s1 = nullptr;
static cudaEvent_t  g_evFork = nullptr, g_evJoin = nullptr;
namespace {
struct StreamInit {
    StreamInit() {
        if (cudaStreamCreateWithFlags(&g_s1, cudaStreamNonBlocking) != cudaSuccess) g_s1 = nullptr;
        if (cudaEventCreateWithFlags(&g_evFork, cudaEventDisableTiming) != cudaSuccess) g_evFork = nullptr;
        if (cudaEventCreateWithFlags(&g_evJoin, cudaEventDisableTiming) != cudaSuccess) g_evJoin = nullptr;
    }
};
StreamInit g_stream_init;
}

__device__ __forceinline__ int load_idx(const void* p, int i, int is64, int N)
{
    int v = is64 ? (int)((const long long*)p)[i] : ((const int*)p)[i];
    return min(max(v, 0), N - 1);
}

__global__ void detect_kernel(const int* __restrict__ src_words)
{
    if (threadIdx.x == 0 && blockIdx.x == 0) {
        int all_zero = 1;
        #pragma unroll 1
        for (int i = 0; i < 64; i++)
            if (src_words[2 * i + 1] != 0) { all_zero = 0; break; }
        g_is64 = all_zero;
    }
}

// ---------------------------------------------------------------------------
// bf16 split helpers
// ---------------------------------------------------------------------------
__device__ __forceinline__ unsigned pack_bf16x2(float lo, float hi)
{
    unsigned r;
    asm("cvt.rn.bf16x2.f32 %0, %1, %2;" : "=r"(r) : "f"(hi), "f"(lo));
    return r;
}

__device__ __forceinline__ void split4(float4 v, uint2& hi, uint2& lo)
{
    unsigned h01 = pack_bf16x2(v.x, v.y);
    unsigned h23 = pack_bf16x2(v.z, v.w);
    float rx = v.x - __uint_as_float(h01 << 16);
    float ry = v.y - __uint_as_float(h01 & 0xffff0000u);
    float rz = v.z - __uint_as_float(h23 << 16);
    float rw = v.w - __uint_as_float(h23 & 0xffff0000u);
    hi = make_uint2(h01, h23);
    lo = make_uint2(pack_bf16x2(rx, ry), pack_bf16x2(rz, rw));
}

// Pre-convert Wfc/Wres to bf16 hi/lo (one float4 per thread).
__global__ void convB_kernel(const float* __restrict__ Wfc,
                             const float* __restrict__ Wres)
{
    int i = blockIdx.x * blockDim.x + threadIdx.x;   // 0..32767
    if (i >= 2 * 256 * 256 / 4) return;
    int mat = i >> 14;
    int r   = i & 16383;
    const float* W = mat ? Wres : Wfc;
    float4 v = *(const float4*)(W + (size_t)r * 4);
    uint2 hi, lo;
    split4(v, hi, lo);
    *(uint2*)&g_Bh[(size_t)i * 4] = hi;
    *(uint2*)&g_Bl[(size_t)i * 4] = lo;
}

// ---------------------------------------------------------------------------
// Tensor-core projection GEMM (bf16 split-precision, 3 mma passes).
//   which==0: C = feat @ W_fc^T          -> g_feat_src
//   which==1: C = feat @ W_res^T + bias  -> rst
// Block tile 64x256, BK=16, 256 threads (8 warps 2x4), warp tile 32x64.
// ---------------------------------------------------------------------------
__device__ __forceinline__ void ldsm_x4(unsigned& r0, unsigned& r1,
                                        unsigned& r2, unsigned& r3, unsigned addr)
{
    asm volatile("ldmatrix.sync.aligned.m8n8.x4.shared.b16 {%0,%1,%2,%3}, [%4];"
                 : "=r"(r0), "=r"(r1), "=r"(r2), "=r"(r3) : "r"(addr));
}

__device__ __forceinline__ void mma_bf16(float* c, const unsigned* a, const unsigned* b)
{
    asm volatile(
        "mma.sync.aligned.m16n8k16.row.col.f32.bf16.bf16.f32 "
        "{%0,%1,%2,%3},{%4,%5,%6,%7},{%8,%9},{%0,%1,%2,%3};"
        : "+f"(c[0]), "+f"(c[1]), "+f"(c[2]), "+f"(c[3])
        : "r"(a[0]), "r"(a[1]), "r"(a[2]), "r"(a[3]), "r"(b[0]), "r"(b[1]));
}

#define SRA 24
#define SRB 24

__global__ void gemm_kernel(const float* __restrict__ feat,
                            const float* __restrict__ bias,
                            float* __restrict__ rst, int N, int which)
{
    __shared__ __align__(16) __nv_bfloat16 Ah[64 * SRA];
    __shared__ __align__(16) __nv_bfloat16 Al[64 * SRA];
    __shared__ __align__(16) __nv_bfloat16 Bh[256 * SRB];
    __shared__ __align__(16) __nv_bfloat16 Bl[256 * SRB];

    const int t      = threadIdx.x;
    const int lane   = t & 31;
    const int warp   = t >> 5;
    const int warp_m = warp >> 2;
    const int warp_n = warp & 3;
    const int m0     = blockIdx.x * 64;
    const bool isfc  = (which == 0);
    const __nv_bfloat16* BHsrc = g_Bh + (isfc ? 0 : 1) * 65536;
    const __nv_bfloat16* BLsrc = g_Bl + (isfc ? 0 : 1) * 65536;

    float acc[2][8][4] = {};

    const int arow = t >> 2;
    const int akq  = (t & 3) * 4;

    float4 pa;
    uint2 pbh[4], pbl[4];
    {
        pa = make_float4(0.f, 0.f, 0.f, 0.f);
        if (m0 + arow < N) pa = *(const float4*)(feat + (size_t)(m0 + arow) * INF_DIM + akq);
        #pragma unroll
        for (int i = 0; i < 4; i++) {
            int lin = t + i * 256;
            int boff = (lin >> 2) * 256 + (lin & 3) * 4;
            pbh[i] = *(const uint2*)(BHsrc + boff);
            pbl[i] = *(const uint2*)(BLsrc + boff);
        }
    }

    const int a_row = (lane & 7) + ((lane >> 3) & 1) * 8;
    const int a_col = (lane >> 4) * 8;
    const int b_row = (lane & 7) + ((lane >> 4) & 1) * 8;
    const int b_col = ((lane >> 3) & 1) * 8;

    unsigned sAh = (unsigned)__cvta_generic_to_shared(Ah);
    unsigned sAl = (unsigned)__cvta_generic_to_shared(Al);
    unsigned sBh = (unsigned)__cvta_generic_to_shared(Bh);
    unsigned sBl = (unsigned)__cvta_generic_to_shared(Bl);

    for (int k0 = 0; k0 < INF_DIM; k0 += 16) {
        {
            uint2 hi, lo;
            split4(pa, hi, lo);
            *(uint2*)&Ah[arow * SRA + akq] = hi;
            *(uint2*)&Al[arow * SRA + akq] = lo;
            #pragma unroll
            for (int i = 0; i < 4; i++) {
                int lin = t + i * 256;
                int brow = lin >> 2, bkq = (lin & 3) * 4;
                *(uint2*)&Bh[brow * SRB + bkq] = pbh[i];
                *(uint2*)&Bl[brow * SRB + bkq] = pbl[i];
            }
        }
        __syncthreads();

        if (k0 + 16 < INF_DIM) {
            pa = make_float4(0.f, 0.f, 0.f, 0.f);
            if (m0 + arow < N)
                pa = *(const float4*)(feat + (size_t)(m0 + arow) * INF_DIM + k0 + 16 + akq);
            #pragma unroll
            for (int i = 0; i < 4; i++) {
                int lin = t + i * 256;
                int boff = (lin >> 2) * 256 + k0 + 16 + (lin & 3) * 4;
                pbh[i] = *(const uint2*)(BHsrc + boff);
                pbl[i] = *(const uint2*)(BLsrc + boff);
            }
        }

        unsigned aH[2][4], aL[2][4], bH[8][2], bL[8][2];
        #pragma unroll
        for (int tm = 0; tm < 2; tm++) {
            int off = ((warp_m * 32 + tm * 16 + a_row) * SRA + a_col) * 2;
            ldsm_x4(aH[tm][0], aH[tm][1], aH[tm][2], aH[tm][3], sAh + off);
            ldsm_x4(aL[tm][0], aL[tm][1], aL[tm][2], aL[tm][3], sAl + off);
        }
        #pragma unroll
        for (int gp = 0; gp < 4; gp++) {
            int off = ((warp_n * 64 + gp * 16 + b_row) * SRB + b_col) * 2;
            ldsm_x4(bH[2*gp][0], bH[2*gp][1], bH[2*gp+1][0], bH[2*gp+1][1], sBh + off);
            ldsm_x4(bL[2*gp][0], bL[2*gp][1], bL[2*gp+1][0], bL[2*gp+1][1], sBl + off);
        }
        #pragma unroll
        for (int tm = 0; tm < 2; tm++)
            #pragma unroll
            for (int ng = 0; ng < 8; ng++) {
                mma_bf16(acc[tm][ng], aH[tm], bH[ng]);
                mma_bf16(acc[tm][ng], aL[tm], bH[ng]);
                mma_bf16(acc[tm][ng], aH[tm], bL[ng]);
            }
        __syncthreads();
    }

    float* outp = isfc ? g_feat_src : rst;
    #pragma unroll
    for (int tm = 0; tm < 2; tm++) {
        int rbase = m0 + warp_m * 32 + tm * 16 + (lane >> 2);
        #pragma unroll
        for (int ng = 0; ng < 8; ng++) {
            int c = warp_n * 64 + ng * 8 + (lane & 3) * 2;
            #pragma unroll
            for (int half = 0; half < 2; half++) {
                int r = rbase + half * 8;
                if (r >= N) continue;
                float v0 = acc[tm][ng][half * 2 + 0];
                float v1 = acc[tm][ng][half * 2 + 1];
                if (!isfc) { v0 += __ldg(bias + c); v1 += __ldg(bias + c + 1); }
                *(float2*)(outp + (size_t)r * INF_DIM + c) = make_float2(v0, v1);
            }
        }
    }
}

// ---------------------------------------------------------------------------
// Per-node attention logits + zero esum. One warp per node.
// ---------------------------------------------------------------------------
__global__ void elr_kernel(const float* __restrict__ attn_l,
                           const float* __restrict__ attn_r, int N)
{
    int node = (int)((blockIdx.x * (size_t)blockDim.x + threadIdx.x) >> 5);
    int lane = threadIdx.x & 31;
    if (node >= N) return;
    const float* fs = g_feat_src + (size_t)node * INF_DIM;
    #pragma unroll
    for (int h = 0; h < HEADS; h++) {
        float v0 = fs[h * 64 + lane];
        float v1 = fs[h * 64 + 32 + lane];
        float sl = v0 * attn_l[h * 64 + lane] + v1 * attn_l[h * 64 + 32 + lane];
        float sr = v0 * attn_r[h * 64 + lane] + v1 * attn_r[h * 64 + 32 + lane];
        #pragma unroll
        for (int o = 16; o; o >>= 1) {
            sl += __shfl_xor_sync(0xffffffffu, sl, o);
            sr += __shfl_xor_sync(0xffffffffu, sr, o);
        }
        if (lane == 0) {
            g_el[node * HEADS + h] = sl;
            g_er[node * HEADS + h] = sr;
        }
    }
    if (lane < HEADS) g_esum[node * HEADS + lane] = 0.f;
}

// ---------------------------------------------------------------------------
// Edge pass: ex = exp(leaky_relu(el[src]+er[dst])); accumulate esum.
// ---------------------------------------------------------------------------
__device__ __forceinline__ float lrelu_exp(float x)
{
    x = (x > 0.f) ? x : 0.05f * x;
    return expf(x);
}

__global__ void edge_kernel(const void* __restrict__ src,
                            const void* __restrict__ dst,
                            float* __restrict__ aout, int E, int N)
{
    int e = blockIdx.x * blockDim.x + threadIdx.x;
    if (e >= E) return;
    int is64 = g_is64;
    int s = load_idx(src, e, is64, N);
    int d = load_idx(dst, e, is64, N);
    float4 el = *(const float4*)(g_el + s * HEADS);
    float4 er = *(const float4*)(g_er + d * HEADS);
    float4 ex;
    ex.x = lrelu_exp(el.x + er.x);
    ex.y = lrelu_exp(el.y + er.y);
    ex.z = lrelu_exp(el.z + er.z);
    ex.w = lrelu_exp(el.w + er.w);
    *(float4*)(aout + (size_t)e * HEADS) = ex;
    asm volatile("red.global.add.v4.f32 [%0], {%1,%2,%3,%4};"
                 :: "l"(g_esum + d * HEADS), "f"(ex.x), "f"(ex.y), "f"(ex.z), "f"(ex.w)
                 : "memory");
}

// ---------------------------------------------------------------------------
// CSR-by-dst build (independent of GEMM; runs on side stream).
// ---------------------------------------------------------------------------
__global__ void zerocnt_kernel(int N)
{
    int i = blockIdx.x * blockDim.x + threadIdx.x;
    if (i < N) g_cnt[i] = 0;
}

__global__ void hist_kernel(const void* __restrict__ dst, int E, int N)
{
    int e = blockIdx.x * blockDim.x + threadIdx.x;
    if (e >= E) return;
    int d = load_idx(dst, e, g_is64, N);
    atomicAdd(&g_cnt[d], 1);
}

__global__ void scan1_kernel(int N)
{
    __shared__ int s[1024];
    int t = threadIdx.x;
    int i = blockIdx.x * 1024 + t;
    int v = (i < N) ? g_cnt[i] : 0;
    s[t] = v;
    __syncthreads();
    #pragma unroll
    for (int o = 1; o < 1024; o <<= 1) {
        int x = (t >= o) ? s[t - o] : 0;
        __syncthreads();
        s[t] += x;
        __syncthreads();
    }
    if (i < N) g_off[i] = s[t];
    if (t == 1023) g_part[blockIdx.x] = s[1023];
}

__global__ void scan2_kernel(int nb)
{
    __shared__ int s[128];
    int t = threadIdx.x;
    int v = (t < nb) ? g_part[t] : 0;
    s[t] = v;
    __syncthreads();
    #pragma unroll
    for (int o = 1; o < 128; o <<= 1) {
        int x = (t >= o) ? s[t - o] : 0;
        __syncthreads();
        s[t] += x;
        __syncthreads();
    }
    if (t < nb) g_part[t] = s[t] - v;
}

__global__ void scan3_kernel(int N)
{
    int i = blockIdx.x * 1024 + threadIdx.x;
    if (i < N) {
        int excl = g_off[i] - g_cnt[i] + g_part[blockIdx.x];
        g_off[i] = excl;
        g_cur[i] = excl;
    }
}

__global__ void scatter_kernel(const void* __restrict__ dst, int E, int N)
{
    int e = blockIdx.x * blockDim.x + threadIdx.x;
    if (e >= E) return;
    int d = load_idx(dst, e, g_is64, N);
    int pos = atomicAdd(&g_cur[d], 1);
    g_csr[pos] = e;
}

// ---------------------------------------------------------------------------
// Aggregation: warp per dst node, chained pull with 1-deep software pipeline:
// next (e, src, ex) prefetched while current feat row gathers.
// ---------------------------------------------------------------------------
__global__ void aggregate_kernel(const void* __restrict__ src,
                                 float* __restrict__ aout,
                                 float* __restrict__ rst, int E, int N)
{
    int n    = (int)((blockIdx.x * (size_t)blockDim.x + threadIdx.x) >> 5);
    int lane = threadIdx.x & 31;
    if (n >= N) return;
    int is64  = g_is64;
    int start = g_off[n];
    int cnt   = g_cnt[n];
    if (cnt == 0) return;

    float su = 1.f;
    if (lane < HEADS) su = fmaxf(g_esum[n * HEADS + lane], 1e-20f);

    float4 accA = make_float4(0.f, 0.f, 0.f, 0.f);
    float4 accB = make_float4(0.f, 0.f, 0.f, 0.f);
    int hA = lane >> 4;
    int hB = 2 + hA;

    // pipeline stage: current (e, s, raw ex)
    int   eC = g_csr[start];
    int   sC = load_idx(src, eC, is64, N);
    float xC = (lane < HEADS) ? aout[(size_t)eC * HEADS + lane] : 0.f;

    for (int j = 0; j < cnt; j++) {
        int   eN = 0, sN = 0;
        float xN = 0.f;
        if (j + 1 < cnt) {
            eN = g_csr[start + j + 1];
            sN = load_idx(src, eN, is64, N);
            if (lane < HEADS) xN = aout[(size_t)eN * HEADS + lane];
        }

        float av = 0.f;
        if (lane < HEADS) {
            av = xC / su;
            aout[(size_t)eC * HEADS + lane] = av;
        }
        float aA = __shfl_sync(0xffffffffu, av, hA);
        float aB = __shfl_sync(0xffffffffu, av, hB);
        const float4* fs4 = (const float4*)(g_feat_src + (size_t)sC * INF_DIM);
        float4 v = fs4[lane];
        float4 w = fs4[lane + 32];
        accA.x += v.x * aA; accA.y += v.y * aA; accA.z += v.z * aA; accA.w += v.w * aA;
        accB.x += w.x * aB; accB.y += w.y * aB; accB.z += w.z * aB; accB.w += w.w * aB;

        eC = eN; sC = sN; xC = xN;
    }

    float4* r4 = (float4*)(rst + (size_t)n * INF_DIM);
    float4 r = r4[lane];
    r.x += accA.x; r.y += accA.y; r.z += accA.z; r.w += accA.w;
    r4[lane] = r;
    float4 q = r4[lane + 32];
    q.x += accB.x; q.y += accB.y; q.z += accB.z; q.w += accB.w;
    r4[lane + 32] = q;
}

extern "C" void kernel_launch(void* const* d_in, const int* in_sizes, int n_in,
                              void* d_out, int out_size)
{
    const float* feat   = (const float*)d_in[0];
    const void*  src    = d_in[1];
    const void*  dst    = d_in[2];
    const float* Wfc    = (const float*)d_in[3];
    const float* attn_l = (const float*)d_in[4];
    const float* attn_r = (const float*)d_in[5];
    const float* Wres   = (const float*)d_in[6];
    const float* bias   = (const float*)d_in[7];

    const int N = in_sizes[0] / INF_DIM;
    const int E = in_sizes[1];

    float* rst = (float*)d_out;
    float* aout;
    if ((long long)out_size >= (long long)N * INF_DIM + (long long)E * HEADS) {
        aout = rst + (size_t)N * INF_DIM;
    } else {
        void* p = nullptr;
        cudaGetSymbolAddress(&p, g_ex);
        aout = (float*)p;
    }

    const int nb = (N + 1023) / 1024;
    const int gemm_blocks = (N + 63) / 64;
    const bool overlap = (g_s1 != nullptr) && (g_evFork != nullptr) && (g_evJoin != nullptr);

    // stream0: prerequisites for both branches
    detect_kernel<<<1, 32>>>((const int*)src);
    convB_kernel<<<128, 256>>>(Wfc, Wres);

    if (overlap) {
        cudaEventRecord(g_evFork, (cudaStream_t)0);
        cudaStreamWaitEvent(g_s1, g_evFork, 0);

        // side stream: CSR build, then the res-projection GEMM (only needed by aggregate)
        zerocnt_kernel<<<(N + 255) / 256, 256, 0, g_s1>>>(N);
        hist_kernel<<<(E + 255) / 256, 256, 0, g_s1>>>(dst, E, N);
        scan1_kernel<<<nb, 1024, 0, g_s1>>>(N);
        scan2_kernel<<<1, 128, 0, g_s1>>>(nb);
        scan3_kernel<<<nb, 1024, 0, g_s1>>>(N);
        scatter_kernel<<<(E + 255) / 256, 256, 0, g_s1>>>(dst, E, N);
        gemm_kernel<<<gemm_blocks, 256, 0, g_s1>>>(feat, bias, rst, N, 1);
        cudaEventRecord(g_evJoin, g_s1);

        // main stream: fc-projection -> logits -> edge softmax numerators
        gemm_kernel<<<gemm_blocks, 256>>>(feat, bias, rst, N, 0);
        elr_kernel<<<(N + 7) / 8, 256>>>(attn_l, attn_r, N);
        edge_kernel<<<(E + 255) / 256, 256>>>(src, dst, aout, E, N);

        cudaStreamWaitEvent((cudaStream_t)0, g_evJoin, 0);
    } else {
        // sequential fallback
        zerocnt_kernel<<<(N + 255) / 256, 256>>>(N);
        hist_kernel<<<(E + 255) / 256, 256>>>(dst, E, N);
        scan1_kernel<<<nb, 1024>>>(N);
        scan2_kernel<<<1, 128>>>(nb);
        scan3_kernel<<<nb, 1024>>>(N);
        scatter_kernel<<<(E + 255) / 256, 256>>>(dst, E, N);
        gemm_kernel<<<gemm_blocks, 256>>>(feat, bias, rst, N, 1);
        gemm_kernel<<<gemm_blocks, 256>>>(feat, bias, rst, N, 0);
        elr_kernel<<<(N + 7) / 8, 256>>>(attn_l, attn_r, N);
        edge_kernel<<<(E + 255) / 256, 256>>>(src, dst, aout, E, N);
    }

    // chained pull aggregation (software-pipelined)
    aggregate_kernel<<<(N + 7) / 8, 256>>>(src, aout, rst, E, N);
}

// round 11
// speedup vs baseline: 1.0908x; 1.0908x over previous
#include <cuda_runtime.h>
#include <cuda_bf16.h>

#define MAXN 100000
#define MAXE 1600000
#define INF_DIM 256     // IN = H*F = 256
#define HEADS 4

// Scratch (device globals; no allocation allowed)
__device__ float g_feat_src[(size_t)MAXN * INF_DIM];
__device__ float g_el[MAXN * HEADS];
__device__ float g_er[MAXN * HEADS];
__device__ float g_esum[MAXN * HEADS];
__device__ float g_ex[(size_t)MAXE * HEADS];   // fallback if 'a' not in d_out
__device__ int   g_is64;
// Pre-converted weights: [2][256 outcol][256 k] bf16 hi/lo
__device__ __nv_bfloat16 g_Bh[2 * 256 * 256];
__device__ __nv_bfloat16 g_Bl[2 * 256 * 256];
// CSR-by-dst scratch
__device__ int g_cnt[MAXN];
__device__ int g_off[MAXN];
__device__ int g_cur[MAXN];
__device__ int g_csr[MAXE];       // edge id grouped by dst
__device__ int g_part[128];

// Side stream + events (module-load init; proven harness-safe).
static cudaStream_t g_s1 = nullptr;
static cudaEvent_t  g_evFork = nullptr, g_evJoin = nullptr;
namespace {
struct StreamInit {
    StreamInit() {
        if (cudaStreamCreateWithFlags(&g_s1, cudaStreamNonBlocking) != cudaSuccess) g_s1 = nullptr;
        if (cudaEventCreateWithFlags(&g_evFork, cudaEventDisableTiming) != cudaSuccess) g_evFork = nullptr;
        if (cudaEventCreateWithFlags(&g_evJoin, cudaEventDisableTiming) != cudaSuccess) g_evJoin = nullptr;
    }
};
StreamInit g_stream_init;
}

__device__ __forceinline__ int load_idx(const void* p, int i, int is64, int N)
{
    int v = is64 ? (int)((const long long*)p)[i] : ((const int*)p)[i];
    return min(max(v, 0), N - 1);
}

__global__ void detect_kernel(const int* __restrict__ src_words)
{
    if (threadIdx.x == 0 && blockIdx.x == 0) {
        int all_zero = 1;
        #pragma unroll 1
        for (int i = 0; i < 64; i++)
            if (src_words[2 * i + 1] != 0) { all_zero = 0; break; }
        g_is64 = all_zero;
    }
}

__global__ void zeroesum_kernel(int n)
{
    int i = blockIdx.x * blockDim.x + threadIdx.x;
    if (i < n) g_esum[i] = 0.f;
}

// ---------------------------------------------------------------------------
// bf16 split helpers
// ---------------------------------------------------------------------------
__device__ __forceinline__ unsigned pack_bf16x2(float lo, float hi)
{
    unsigned r;
    asm("cvt.rn.bf16x2.f32 %0, %1, %2;" : "=r"(r) : "f"(hi), "f"(lo));
    return r;
}

__device__ __forceinline__ void split4(float4 v, uint2& hi, uint2& lo)
{
    unsigned h01 = pack_bf16x2(v.x, v.y);
    unsigned h23 = pack_bf16x2(v.z, v.w);
    float rx = v.x - __uint_as_float(h01 << 16);
    float ry = v.y - __uint_as_float(h01 & 0xffff0000u);
    float rz = v.z - __uint_as_float(h23 << 16);
    float rw = v.w - __uint_as_float(h23 & 0xffff0000u);
    hi = make_uint2(h01, h23);
    lo = make_uint2(pack_bf16x2(rx, ry), pack_bf16x2(rz, rw));
}

// Pre-convert Wfc/Wres to bf16 hi/lo (one float4 per thread).
__global__ void convB_kernel(const float* __restrict__ Wfc,
                             const float* __restrict__ Wres)
{
    int i = blockIdx.x * blockDim.x + threadIdx.x;   // 0..32767
    if (i >= 2 * 256 * 256 / 4) return;
    int mat = i >> 14;
    int r   = i & 16383;
    const float* W = mat ? Wres : Wfc;
    float4 v = *(const float4*)(W + (size_t)r * 4);
    uint2 hi, lo;
    split4(v, hi, lo);
    *(uint2*)&g_Bh[(size_t)i * 4] = hi;
    *(uint2*)&g_Bl[(size_t)i * 4] = lo;
}

// ---------------------------------------------------------------------------
// Tensor-core projection GEMM (bf16 split-precision, 3 mma passes):
//   blockIdx.x==0: C = feat @ W_fc^T          -> g_feat_src, + fused el/er
//   blockIdx.x==1: C = feat @ W_res^T + bias  -> rst
// Block tile 64x256, BK=16, 256 threads (8 warps 2x4), warp tile 32x64.
// Fused elr: each warp's 64 output cols are exactly one head (head==warp_n),
// so el/er reduce in-register + 2 shfl steps; no feat_src re-read.
// ---------------------------------------------------------------------------
__device__ __forceinline__ void ldsm_x4(unsigned& r0, unsigned& r1,
                                        unsigned& r2, unsigned& r3, unsigned addr)
{
    asm volatile("ldmatrix.sync.aligned.m8n8.x4.shared.b16 {%0,%1,%2,%3}, [%4];"
                 : "=r"(r0), "=r"(r1), "=r"(r2), "=r"(r3) : "r"(addr));
}

__device__ __forceinline__ void mma_bf16(float* c, const unsigned* a, const unsigned* b)
{
    asm volatile(
        "mma.sync.aligned.m16n8k16.row.col.f32.bf16.bf16.f32 "
        "{%0,%1,%2,%3},{%4,%5,%6,%7},{%8,%9},{%0,%1,%2,%3};"
        : "+f"(c[0]), "+f"(c[1]), "+f"(c[2]), "+f"(c[3])
        : "r"(a[0]), "r"(a[1]), "r"(a[2]), "r"(a[3]), "r"(b[0]), "r"(b[1]));
}

#define SRA 24
#define SRB 24

__global__ void gemm_kernel(const float* __restrict__ feat,
                            const float* __restrict__ bias,
                            const float* __restrict__ attn_l,
                            const float* __restrict__ attn_r,
                            float* __restrict__ rst, int N)
{
    __shared__ __align__(16) __nv_bfloat16 Ah[64 * SRA];
    __shared__ __align__(16) __nv_bfloat16 Al[64 * SRA];
    __shared__ __align__(16) __nv_bfloat16 Bh[256 * SRB];
    __shared__ __align__(16) __nv_bfloat16 Bl[256 * SRB];

    const int t      = threadIdx.x;
    const int lane   = t & 31;
    const int warp   = t >> 5;
    const int warp_m = warp >> 2;
    const int warp_n = warp & 3;
    const int m0     = blockIdx.y * 64;
    const bool isfc  = (blockIdx.x == 0);
    const __nv_bfloat16* BHsrc = g_Bh + (isfc ? 0 : 1) * 65536;
    const __nv_bfloat16* BLsrc = g_Bl + (isfc ? 0 : 1) * 65536;

    float acc[2][8][4] = {};

    const int arow = t >> 2;
    const int akq  = (t & 3) * 4;

    float4 pa;
    uint2 pbh[4], pbl[4];
    {
        pa = make_float4(0.f, 0.f, 0.f, 0.f);
        if (m0 + arow < N) pa = *(const float4*)(feat + (size_t)(m0 + arow) * INF_DIM + akq);
        #pragma unroll
        for (int i = 0; i < 4; i++) {
            int lin = t + i * 256;
            int boff = (lin >> 2) * 256 + (lin & 3) * 4;
            pbh[i] = *(const uint2*)(BHsrc + boff);
            pbl[i] = *(const uint2*)(BLsrc + boff);
        }
    }

    const int a_row = (lane & 7) + ((lane >> 3) & 1) * 8;
    const int a_col = (lane >> 4) * 8;
    const int b_row = (lane & 7) + ((lane >> 4) & 1) * 8;
    const int b_col = ((lane >> 3) & 1) * 8;

    unsigned sAh = (unsigned)__cvta_generic_to_shared(Ah);
    unsigned sAl = (unsigned)__cvta_generic_to_shared(Al);
    unsigned sBh = (unsigned)__cvta_generic_to_shared(Bh);
    unsigned sBl = (unsigned)__cvta_generic_to_shared(Bl);

    for (int k0 = 0; k0 < INF_DIM; k0 += 16) {
        {
            uint2 hi, lo;
            split4(pa, hi, lo);
            *(uint2*)&Ah[arow * SRA + akq] = hi;
            *(uint2*)&Al[arow * SRA + akq] = lo;
            #pragma unroll
            for (int i = 0; i < 4; i++) {
                int lin = t + i * 256;
                int brow = lin >> 2, bkq = (lin & 3) * 4;
                *(uint2*)&Bh[brow * SRB + bkq] = pbh[i];
                *(uint2*)&Bl[brow * SRB + bkq] = pbl[i];
            }
        }
        __syncthreads();

        if (k0 + 16 < INF_DIM) {
            pa = make_float4(0.f, 0.f, 0.f, 0.f);
            if (m0 + arow < N)
                pa = *(const float4*)(feat + (size_t)(m0 + arow) * INF_DIM + k0 + 16 + akq);
            #pragma unroll
            for (int i = 0; i < 4; i++) {
                int lin = t + i * 256;
                int boff = (lin >> 2) * 256 + k0 + 16 + (lin & 3) * 4;
                pbh[i] = *(const uint2*)(BHsrc + boff);
                pbl[i] = *(const uint2*)(BLsrc + boff);
            }
        }

        unsigned aH[2][4], aL[2][4], bH[8][2], bL[8][2];
        #pragma unroll
        for (int tm = 0; tm < 2; tm++) {
            int off = ((warp_m * 32 + tm * 16 + a_row) * SRA + a_col) * 2;
            ldsm_x4(aH[tm][0], aH[tm][1], aH[tm][2], aH[tm][3], sAh + off);
            ldsm_x4(aL[tm][0], aL[tm][1], aL[tm][2], aL[tm][3], sAl + off);
        }
        #pragma unroll
        for (int gp = 0; gp < 4; gp++) {
            int off = ((warp_n * 64 + gp * 16 + b_row) * SRB + b_col) * 2;
            ldsm_x4(bH[2*gp][0], bH[2*gp][1], bH[2*gp+1][0], bH[2*gp+1][1], sBh + off);
            ldsm_x4(bL[2*gp][0], bL[2*gp][1], bL[2*gp+1][0], bL[2*gp+1][1], sBl + off);
        }
        #pragma unroll
        for (int tm = 0; tm < 2; tm++)
            #pragma unroll
            for (int ng = 0; ng < 8; ng++) {
                mma_bf16(acc[tm][ng], aH[tm], bH[ng]);
                mma_bf16(acc[tm][ng], aL[tm], bH[ng]);
                mma_bf16(acc[tm][ng], aH[tm], bL[ng]);
            }
        __syncthreads();
    }

    // ---- epilogue ----
    float* outp = isfc ? g_feat_src : rst;
    #pragma unroll
    for (int tm = 0; tm < 2; tm++) {
        int rbase = m0 + warp_m * 32 + tm * 16 + (lane >> 2);
        #pragma unroll
        for (int ng = 0; ng < 8; ng++) {
            int c = warp_n * 64 + ng * 8 + (lane & 3) * 2;
            #pragma unroll
            for (int half = 0; half < 2; half++) {
                int r = rbase + half * 8;
                if (r >= N) continue;
                float v0 = acc[tm][ng][half * 2 + 0];
                float v1 = acc[tm][ng][half * 2 + 1];
                if (!isfc) { v0 += __ldg(bias + c); v1 += __ldg(bias + c + 1); }
                *(float2*)(outp + (size_t)r * INF_DIM + c) = make_float2(v0, v1);
            }
        }
    }

    // ---- fused el/er (fc half only): head == warp_n ----
    if (isfc) {
        #pragma unroll
        for (int tm = 0; tm < 2; tm++) {
            #pragma unroll
            for (int half = 0; half < 2; half++) {
                float sl = 0.f, sr = 0.f;
                #pragma unroll
                for (int ng = 0; ng < 8; ng++) {
                    int c = warp_n * 64 + ng * 8 + (lane & 3) * 2;
                    float v0 = acc[tm][ng][half * 2 + 0];
                    float v1 = acc[tm][ng][half * 2 + 1];
                    sl += v0 * __ldg(attn_l + c) + v1 * __ldg(attn_l + c + 1);
                    sr += v0 * __ldg(attn_r + c) + v1 * __ldg(attn_r + c + 1);
                }
                // reduce over the 4 lanes (lane&3) that share this row
                sl += __shfl_xor_sync(0xffffffffu, sl, 1);
                sr += __shfl_xor_sync(0xffffffffu, sr, 1);
                sl += __shfl_xor_sync(0xffffffffu, sl, 2);
                sr += __shfl_xor_sync(0xffffffffu, sr, 2);
                int r = m0 + warp_m * 32 + tm * 16 + (lane >> 2) + half * 8;
                if ((lane & 3) == 0 && r < N) {
                    g_el[r * HEADS + warp_n] = sl;
                    g_er[r * HEADS + warp_n] = sr;
                }
            }
        }
    }
}

// ---------------------------------------------------------------------------
// Edge pass: ex = exp(leaky_relu(el[src]+er[dst])); accumulate esum.
// ---------------------------------------------------------------------------
__device__ __forceinline__ float lrelu_exp(float x)
{
    x = (x > 0.f) ? x : 0.05f * x;
    return expf(x);
}

__global__ void edge_kernel(const void* __restrict__ src,
                            const void* __restrict__ dst,
                            float* __restrict__ aout, int E, int N)
{
    int e = blockIdx.x * blockDim.x + threadIdx.x;
    if (e >= E) return;
    int is64 = g_is64;
    int s = load_idx(src, e, is64, N);
    int d = load_idx(dst, e, is64, N);
    float4 el = *(const float4*)(g_el + s * HEADS);
    float4 er = *(const float4*)(g_er + d * HEADS);
    float4 ex;
    ex.x = lrelu_exp(el.x + er.x);
    ex.y = lrelu_exp(el.y + er.y);
    ex.z = lrelu_exp(el.z + er.z);
    ex.w = lrelu_exp(el.w + er.w);
    *(float4*)(aout + (size_t)e * HEADS) = ex;
    asm volatile("red.global.add.v4.f32 [%0], {%1,%2,%3,%4};"
                 :: "l"(g_esum + d * HEADS), "f"(ex.x), "f"(ex.y), "f"(ex.z), "f"(ex.w)
                 : "memory");
}

// ---------------------------------------------------------------------------
// CSR-by-dst build (independent of GEMM; runs on side stream).
// ---------------------------------------------------------------------------
__global__ void zerocnt_kernel(int N)
{
    int i = blockIdx.x * blockDim.x + threadIdx.x;
    if (i < N) g_cnt[i] = 0;
}

__global__ void hist_kernel(const void* __restrict__ dst, int E, int N)
{
    int e = blockIdx.x * blockDim.x + threadIdx.x;
    if (e >= E) return;
    int d = load_idx(dst, e, g_is64, N);
    atomicAdd(&g_cnt[d], 1);
}

__global__ void scan1_kernel(int N)
{
    __shared__ int s[1024];
    int t = threadIdx.x;
    int i = blockIdx.x * 1024 + t;
    int v = (i < N) ? g_cnt[i] : 0;
    s[t] = v;
    __syncthreads();
    #pragma unroll
    for (int o = 1; o < 1024; o <<= 1) {
        int x = (t >= o) ? s[t - o] : 0;
        __syncthreads();
        s[t] += x;
        __syncthreads();
    }
    if (i < N) g_off[i] = s[t];
    if (t == 1023) g_part[blockIdx.x] = s[1023];
}

__global__ void scan2_kernel(int nb)
{
    __shared__ int s[128];
    int t = threadIdx.x;
    int v = (t < nb) ? g_part[t] : 0;
    s[t] = v;
    __syncthreads();
    #pragma unroll
    for (int o = 1; o < 128; o <<= 1) {
        int x = (t >= o) ? s[t - o] : 0;
        __syncthreads();
        s[t] += x;
        __syncthreads();
    }
    if (t < nb) g_part[t] = s[t] - v;
}

__global__ void scan3_kernel(int N)
{
    int i = blockIdx.x * 1024 + threadIdx.x;
    if (i < N) {
        int excl = g_off[i] - g_cnt[i] + g_part[blockIdx.x];
        g_off[i] = excl;
        g_cur[i] = excl;
    }
}

__global__ void scatter_kernel(const void* __restrict__ dst, int E, int N)
{
    int e = blockIdx.x * blockDim.x + threadIdx.x;
    if (e >= E) return;
    int d = load_idx(dst, e, g_is64, N);
    int pos = atomicAdd(&g_cur[d], 1);
    g_csr[pos] = e;
}

// ---------------------------------------------------------------------------
// Aggregation (R9 best-known): warp per dst node, chained pull.
// ---------------------------------------------------------------------------
__global__ void aggregate_kernel(const void* __restrict__ src,
                                 float* __restrict__ aout,
                                 float* __restrict__ rst, int E, int N)
{
    int n    = (int)((blockIdx.x * (size_t)blockDim.x + threadIdx.x) >> 5);
    int lane = threadIdx.x & 31;
    if (n >= N) return;
    int is64  = g_is64;
    int start = g_off[n];
    int cnt   = g_cnt[n];

    float su = 1.f;
    if (lane < HEADS) su = fmaxf(g_esum[n * HEADS + lane], 1e-20f);

    float4 accA = make_float4(0.f, 0.f, 0.f, 0.f);
    float4 accB = make_float4(0.f, 0.f, 0.f, 0.f);
    int hA = lane >> 4;
    int hB = 2 + hA;

    for (int j = 0; j < cnt; j++) {
        int e = g_csr[start + j];
        int s = load_idx(src, e, is64, N);
        float av = 0.f;
        if (lane < HEADS) {
            av = aout[(size_t)e * HEADS + lane] / su;
            aout[(size_t)e * HEADS + lane] = av;
        }
        float aA = __shfl_sync(0xffffffffu, av, hA);
        float aB = __shfl_sync(0xffffffffu, av, hB);
        const float4* fs4 = (const float4*)(g_feat_src + (size_t)s * INF_DIM);
        float4 v = fs4[lane];
        float4 w = fs4[lane + 32];
        accA.x += v.x * aA; accA.y += v.y * aA; accA.z += v.z * aA; accA.w += v.w * aA;
        accB.x += w.x * aB; accB.y += w.y * aB; accB.z += w.z * aB; accB.w += w.w * aB;
    }

    float4* r4 = (float4*)(rst + (size_t)n * INF_DIM);
    if (cnt > 0) {
        float4 r = r4[lane];
        r.x += accA.x; r.y += accA.y; r.z += accA.z; r.w += accA.w;
        r4[lane] = r;
        float4 q = r4[lane + 32];
        q.x += accB.x; q.y += accB.y; q.z += accB.z; q.w += accB.w;
        r4[lane + 32] = q;
    }
}

extern "C" void kernel_launch(void* const* d_in, const int* in_sizes, int n_in,
                              void* d_out, int out_size)
{
    const float* feat   = (const float*)d_in[0];
    const void*  src    = d_in[1];
    const void*  dst    = d_in[2];
    const float* Wfc    = (const float*)d_in[3];
    const float* attn_l = (const float*)d_in[4];
    const float* attn_r = (const float*)d_in[5];
    const float* Wres   = (const float*)d_in[6];
    const float* bias   = (const float*)d_in[7];

    const int N = in_sizes[0] / INF_DIM;
    const int E = in_sizes[1];

    float* rst = (float*)d_out;
    float* aout;
    if ((long long)out_size >= (long long)N * INF_DIM + (long long)E * HEADS) {
        aout = rst + (size_t)N * INF_DIM;
    } else {
        void* p = nullptr;
        cudaGetSymbolAddress(&p, g_ex);
        aout = (float*)p;
    }

    const int nb = (N + 1023) / 1024;
    const bool overlap = (g_s1 != nullptr) && (g_evFork != nullptr) && (g_evJoin != nullptr);
    cudaStream_t sb = overlap ? g_s1 : (cudaStream_t)0;

    // 0) index dtype probe
    detect_kernel<<<1, 32>>>((const int*)src);

    if (overlap) {
        cudaEventRecord(g_evFork, (cudaStream_t)0);
        cudaStreamWaitEvent(g_s1, g_evFork, 0);
    }

    // --- side stream: CSR-by-dst build (independent of GEMM) ---
    zerocnt_kernel<<<(N + 255) / 256, 256, 0, sb>>>(N);
    hist_kernel<<<(E + 255) / 256, 256, 0, sb>>>(dst, E, N);
    scan1_kernel<<<nb, 1024, 0, sb>>>(N);
    scan2_kernel<<<1, 128, 0, sb>>>(nb);
    scan3_kernel<<<nb, 1024, 0, sb>>>(N);
    scatter_kernel<<<(E + 255) / 256, 256, 0, sb>>>(dst, E, N);
    if (overlap) cudaEventRecord(g_evJoin, g_s1);

    // --- main stream: pre-convert + esum zero -> GEMM(+fused elr) -> edges ---
    convB_kernel<<<128, 256>>>(Wfc, Wres);
    zeroesum_kernel<<<(N * HEADS + 255) / 256, 256>>>(N * HEADS);
    dim3 ggrid(2, (N + 63) / 64);
    gemm_kernel<<<ggrid, 256>>>(feat, bias, attn_l, attn_r, rst, N);
    edge_kernel<<<(E + 255) / 256, 256>>>(src, dst, aout, E, N);

    if (overlap) cudaStreamWaitEvent((cudaStream_t)0, g_evJoin, 0);

    // --- chained pull aggregation (best known) ---
    aggregate_kernel<<<(N + 7) / 8, 256>>>(src, aout, rst, E, N);
}

// round 13
// speedup vs baseline: 1.1834x; 1.0849x over previous
#include <cuda_runtime.h>
#include <cuda_bf16.h>

#define MAXN 100000
#define MAXE 1600000
#define INF_DIM 256     // IN = H*F = 256
#define HEADS 4

// Scratch (device globals; no allocation allowed)
__device__ float g_feat_src[(size_t)MAXN * INF_DIM];
__device__ float g_el[MAXN * HEADS];
__device__ float g_er[MAXN * HEADS];
__device__ float g_esum[MAXN * HEADS];
__device__ float g_ex[(size_t)MAXE * HEADS];   // fallback if 'a' not in d_out
__device__ int   g_is64;
// Pre-converted weights: [2][256 outcol][256 k] bf16 hi/lo
__device__ __nv_bfloat16 g_Bh[2 * 256 * 256];
__device__ __nv_bfloat16 g_Bl[2 * 256 * 256];
// CSR-by-dst scratch
__device__ int g_cnt[MAXN];
__device__ int g_off[MAXN];
__device__ int g_cur[MAXN];
__device__ int g_csr[MAXE];       // edge id grouped by dst
__device__ int g_part[128];

// Side stream + events (module-load init; proven harness-safe).
static cudaStream_t g_s1 = nullptr;
static cudaEvent_t  g_evFork = nullptr, g_evJoin = nullptr;
namespace {
struct StreamInit {
    StreamInit() {
        if (cudaStreamCreateWithFlags(&g_s1, cudaStreamNonBlocking) != cudaSuccess) g_s1 = nullptr;
        if (cudaEventCreateWithFlags(&g_evFork, cudaEventDisableTiming) != cudaSuccess) g_evFork = nullptr;
        if (cudaEventCreateWithFlags(&g_evJoin, cudaEventDisableTiming) != cudaSuccess) g_evJoin = nullptr;
    }
};
StreamInit g_stream_init;
}

__device__ __forceinline__ int load_idx(const void* p, int i, int is64, int N)
{
    int v = is64 ? (int)((const long long*)p)[i] : ((const int*)p)[i];
    return min(max(v, 0), N - 1);
}

__global__ void detect_kernel(const int* __restrict__ src_words)
{
    if (threadIdx.x == 0 && blockIdx.x == 0) {
        int all_zero = 1;
        #pragma unroll 1
        for (int i = 0; i < 64; i++)
            if (src_words[2 * i + 1] != 0) { all_zero = 0; break; }
        g_is64 = all_zero;
    }
}

__global__ void zeroesum_kernel(int n)
{
    int i = blockIdx.x * blockDim.x + threadIdx.x;
    if (i < n) g_esum[i] = 0.f;
}

// ---------------------------------------------------------------------------
// bf16 split helpers
// ---------------------------------------------------------------------------
__device__ __forceinline__ unsigned pack_bf16x2(float lo, float hi)
{
    unsigned r;
    asm("cvt.rn.bf16x2.f32 %0, %1, %2;" : "=r"(r) : "f"(hi), "f"(lo));
    return r;
}

__device__ __forceinline__ void split4(float4 v, uint2& hi, uint2& lo)
{
    unsigned h01 = pack_bf16x2(v.x, v.y);
    unsigned h23 = pack_bf16x2(v.z, v.w);
    float rx = v.x - __uint_as_float(h01 << 16);
    float ry = v.y - __uint_as_float(h01 & 0xffff0000u);
    float rz = v.z - __uint_as_float(h23 << 16);
    float rw = v.w - __uint_as_float(h23 & 0xffff0000u);
    hi = make_uint2(h01, h23);
    lo = make_uint2(pack_bf16x2(rx, ry), pack_bf16x2(rz, rw));
}

// Pre-convert Wfc/Wres to bf16 hi/lo (one float4 per thread).
__global__ void convB_kernel(const float* __restrict__ Wfc,
                             const float* __restrict__ Wres)
{
    int i = blockIdx.x * blockDim.x + threadIdx.x;   // 0..32767
    if (i >= 2 * 256 * 256 / 4) return;
    int mat = i >> 14;
    int r   = i & 16383;
    const float* W = mat ? Wres : Wfc;
    float4 v = *(const float4*)(W + (size_t)r * 4);
    uint2 hi, lo;
    split4(v, hi, lo);
    *(uint2*)&g_Bh[(size_t)i * 4] = hi;
    *(uint2*)&g_Bl[(size_t)i * 4] = lo;
}

// ---------------------------------------------------------------------------
// Tensor-core projection GEMM (bf16 split-precision, 3 mma passes):
//   blockIdx.x==0: C = feat @ W_fc^T          -> g_feat_src, + fused el/er
//   blockIdx.x==1: C = feat @ W_res^T + bias  -> rst
// Block tile 64x256, BK=16, 256 threads (8 warps 2x4), warp tile 32x64.
// ---------------------------------------------------------------------------
__device__ __forceinline__ void ldsm_x4(unsigned& r0, unsigned& r1,
                                        unsigned& r2, unsigned& r3, unsigned addr)
{
    asm volatile("ldmatrix.sync.aligned.m8n8.x4.shared.b16 {%0,%1,%2,%3}, [%4];"
                 : "=r"(r0), "=r"(r1), "=r"(r2), "=r"(r3) : "r"(addr));
}

__device__ __forceinline__ void mma_bf16(float* c, const unsigned* a, const unsigned* b)
{
    asm volatile(
        "mma.sync.aligned.m16n8k16.row.col.f32.bf16.bf16.f32 "
        "{%0,%1,%2,%3},{%4,%5,%6,%7},{%8,%9},{%0,%1,%2,%3};"
        : "+f"(c[0]), "+f"(c[1]), "+f"(c[2]), "+f"(c[3])
        : "r"(a[0]), "r"(a[1]), "r"(a[2]), "r"(a[3]), "r"(b[0]), "r"(b[1]));
}

#define SRA 24
#define SRB 24

__global__ void gemm_kernel(const float* __restrict__ feat,
                            const float* __restrict__ bias,
                            const float* __restrict__ attn_l,
                            const float* __restrict__ attn_r,
                            float* __restrict__ rst, int N)
{
    __shared__ __align__(16) __nv_bfloat16 Ah[64 * SRA];
    __shared__ __align__(16) __nv_bfloat16 Al[64 * SRA];
    __shared__ __align__(16) __nv_bfloat16 Bh[256 * SRB];
    __shared__ __align__(16) __nv_bfloat16 Bl[256 * SRB];

    const int t      = threadIdx.x;
    const int lane   = t & 31;
    const int warp   = t >> 5;
    const int warp_m = warp >> 2;
    const int warp_n = warp & 3;
    const int m0     = blockIdx.y * 64;
    const bool isfc  = (blockIdx.x == 0);
    const __nv_bfloat16* BHsrc = g_Bh + (isfc ? 0 : 1) * 65536;
    const __nv_bfloat16* BLsrc = g_Bl + (isfc ? 0 : 1) * 65536;

    float acc[2][8][4] = {};

    const int arow = t >> 2;
    const int akq  = (t & 3) * 4;

    float4 pa;
    uint2 pbh[4], pbl[4];
    {
        pa = make_float4(0.f, 0.f, 0.f, 0.f);
        if (m0 + arow < N) pa = *(const float4*)(feat + (size_t)(m0 + arow) * INF_DIM + akq);
        #pragma unroll
        for (int i = 0; i < 4; i++) {
            int lin = t + i * 256;
            int boff = (lin >> 2) * 256 + (lin & 3) * 4;
            pbh[i] = *(const uint2*)(BHsrc + boff);
            pbl[i] = *(const uint2*)(BLsrc + boff);
        }
    }

    const int a_row = (lane & 7) + ((lane >> 3) & 1) * 8;
    const int a_col = (lane >> 4) * 8;
    const int b_row = (lane & 7) + ((lane >> 4) & 1) * 8;
    const int b_col = ((lane >> 3) & 1) * 8;

    unsigned sAh = (unsigned)__cvta_generic_to_shared(Ah);
    unsigned sAl = (unsigned)__cvta_generic_to_shared(Al);
    unsigned sBh = (unsigned)__cvta_generic_to_shared(Bh);
    unsigned sBl = (unsigned)__cvta_generic_to_shared(Bl);

    for (int k0 = 0; k0 < INF_DIM; k0 += 16) {
        {
            uint2 hi, lo;
            split4(pa, hi, lo);
            *(uint2*)&Ah[arow * SRA + akq] = hi;
            *(uint2*)&Al[arow * SRA + akq] = lo;
            #pragma unroll
            for (int i = 0; i < 4; i++) {
                int lin = t + i * 256;
                int brow = lin >> 2, bkq = (lin & 3) * 4;
                *(uint2*)&Bh[brow * SRB + bkq] = pbh[i];
                *(uint2*)&Bl[brow * SRB + bkq] = pbl[i];
            }
        }
        __syncthreads();

        if (k0 + 16 < INF_DIM) {
            pa = make_float4(0.f, 0.f, 0.f, 0.f);
            if (m0 + arow < N)
                pa = *(const float4*)(feat + (size_t)(m0 + arow) * INF_DIM + k0 + 16 + akq);
            #pragma unroll
            for (int i = 0; i < 4; i++) {
                int lin = t + i * 256;
                int boff = (lin >> 2) * 256 + k0 + 16 + (lin & 3) * 4;
                pbh[i] = *(const uint2*)(BHsrc + boff);
                pbl[i] = *(const uint2*)(BLsrc + boff);
            }
        }

        unsigned aH[2][4], aL[2][4], bH[8][2], bL[8][2];
        #pragma unroll
        for (int tm = 0; tm < 2; tm++) {
            int off = ((warp_m * 32 + tm * 16 + a_row) * SRA + a_col) * 2;
            ldsm_x4(aH[tm][0], aH[tm][1], aH[tm][2], aH[tm][3], sAh + off);
            ldsm_x4(aL[tm][0], aL[tm][1], aL[tm][2], aL[tm][3], sAl + off);
        }
        #pragma unroll
        for (int gp = 0; gp < 4; gp++) {
            int off = ((warp_n * 64 + gp * 16 + b_row) * SRB + b_col) * 2;
            ldsm_x4(bH[2*gp][0], bH[2*gp][1], bH[2*gp+1][0], bH[2*gp+1][1], sBh + off);
            ldsm_x4(bL[2*gp][0], bL[2*gp][1], bL[2*gp+1][0], bL[2*gp+1][1], sBl + off);
        }
        #pragma unroll
        for (int tm = 0; tm < 2; tm++)
            #pragma unroll
            for (int ng = 0; ng < 8; ng++) {
                mma_bf16(acc[tm][ng], aH[tm], bH[ng]);
                mma_bf16(acc[tm][ng], aL[tm], bH[ng]);
                mma_bf16(acc[tm][ng], aH[tm], bL[ng]);
            }
        __syncthreads();
    }

    // ---- epilogue ----
    float* outp = isfc ? g_feat_src : rst;
    #pragma unroll
    for (int tm = 0; tm < 2; tm++) {
        int rbase = m0 + warp_m * 32 + tm * 16 + (lane >> 2);
        #pragma unroll
        for (int ng = 0; ng < 8; ng++) {
            int c = warp_n * 64 + ng * 8 + (lane & 3) * 2;
            #pragma unroll
            for (int half = 0; half < 2; half++) {
                int r = rbase + half * 8;
                if (r >= N) continue;
                float v0 = acc[tm][ng][half * 2 + 0];
                float v1 = acc[tm][ng][half * 2 + 1];
                if (!isfc) { v0 += __ldg(bias + c); v1 += __ldg(bias + c + 1); }
                *(float2*)(outp + (size_t)r * INF_DIM + c) = make_float2(v0, v1);
            }
        }
    }

    // ---- fused el/er (fc half only): head == warp_n ----
    if (isfc) {
        #pragma unroll
        for (int tm = 0; tm < 2; tm++) {
            #pragma unroll
            for (int half = 0; half < 2; half++) {
                float sl = 0.f, sr = 0.f;
                #pragma unroll
                for (int ng = 0; ng < 8; ng++) {
                    int c = warp_n * 64 + ng * 8 + (lane & 3) * 2;
                    float v0 = acc[tm][ng][half * 2 + 0];
                    float v1 = acc[tm][ng][half * 2 + 1];
                    sl += v0 * __ldg(attn_l + c) + v1 * __ldg(attn_l + c + 1);
                    sr += v0 * __ldg(attn_r + c) + v1 * __ldg(attn_r + c + 1);
                }
                sl += __shfl_xor_sync(0xffffffffu, sl, 1);
                sr += __shfl_xor_sync(0xffffffffu, sr, 1);
                sl += __shfl_xor_sync(0xffffffffu, sl, 2);
                sr += __shfl_xor_sync(0xffffffffu, sr, 2);
                int r = m0 + warp_m * 32 + tm * 16 + (lane >> 2) + half * 8;
                if ((lane & 3) == 0 && r < N) {
                    g_el[r * HEADS + warp_n] = sl;
                    g_er[r * HEADS + warp_n] = sr;
                }
            }
        }
    }
}

// ---------------------------------------------------------------------------
// Edge pass: ex = exp(leaky_relu(el[src]+er[dst])); accumulate esum.
// ---------------------------------------------------------------------------
__device__ __forceinline__ float lrelu_exp(float x)
{
    x = (x > 0.f) ? x : 0.05f * x;
    return expf(x);
}

__global__ void edge_kernel(const void* __restrict__ src,
                            const void* __restrict__ dst,
                            float* __restrict__ aout, int E, int N)
{
    int e = blockIdx.x * blockDim.x + threadIdx.x;
    if (e >= E) return;
    int is64 = g_is64;
    int s = load_idx(src, e, is64, N);
    int d = load_idx(dst, e, is64, N);
    float4 el = *(const float4*)(g_el + s * HEADS);
    float4 er = *(const float4*)(g_er + d * HEADS);
    float4 ex;
    ex.x = lrelu_exp(el.x + er.x);
    ex.y = lrelu_exp(el.y + er.y);
    ex.z = lrelu_exp(el.z + er.z);
    ex.w = lrelu_exp(el.w + er.w);
    *(float4*)(aout + (size_t)e * HEADS) = ex;
    asm volatile("red.global.add.v4.f32 [%0], {%1,%2,%3,%4};"
                 :: "l"(g_esum + d * HEADS), "f"(ex.x), "f"(ex.y), "f"(ex.z), "f"(ex.w)
                 : "memory");
}

// ---------------------------------------------------------------------------
// CSR-by-dst build (independent of GEMM; runs on side stream).
// ---------------------------------------------------------------------------
__global__ void zerocnt_kernel(int N)
{
    int i = blockIdx.x * blockDim.x + threadIdx.x;
    if (i < N) g_cnt[i] = 0;
}

__global__ void hist_kernel(const void* __restrict__ dst, int E, int N)
{
    int e = blockIdx.x * blockDim.x + threadIdx.x;
    if (e >= E) return;
    int d = load_idx(dst, e, g_is64, N);
    atomicAdd(&g_cnt[d], 1);
}

__global__ void scan1_kernel(int N)
{
    __shared__ int s[1024];
    int t = threadIdx.x;
    int i = blockIdx.x * 1024 + t;
    int v = (i < N) ? g_cnt[i] : 0;
    s[t] = v;
    __syncthreads();
    #pragma unroll
    for (int o = 1; o < 1024; o <<= 1) {
        int x = (t >= o) ? s[t - o] : 0;
        __syncthreads();
        s[t] += x;
        __syncthreads();
    }
    if (i < N) g_off[i] = s[t];
    if (t == 1023) g_part[blockIdx.x] = s[1023];
}

__global__ void scan2_kernel(int nb)
{
    __shared__ int s[128];
    int t = threadIdx.x;
    int v = (t < nb) ? g_part[t] : 0;
    s[t] = v;
    __syncthreads();
    #pragma unroll
    for (int o = 1; o < 128; o <<= 1) {
        int x = (t >= o) ? s[t - o] : 0;
        __syncthreads();
        s[t] += x;
        __syncthreads();
    }
    if (t < nb) g_part[t] = s[t] - v;
}

__global__ void scan3_kernel(int N)
{
    int i = blockIdx.x * 1024 + threadIdx.x;
    if (i < N) {
        int excl = g_off[i] - g_cnt[i] + g_part[blockIdx.x];
        g_off[i] = excl;
        g_cur[i] = excl;
    }
}

__global__ void scatter_kernel(const void* __restrict__ dst, int E, int N)
{
    int e = blockIdx.x * blockDim.x + threadIdx.x;
    if (e >= E) return;
    int d = load_idx(dst, e, g_is64, N);
    int pos = atomicAdd(&g_cur[d], 1);
    g_csr[pos] = e;
}

// ---------------------------------------------------------------------------
// Aggregation: warp per dst node, chained pull, 2-way unrolled so two
// independent feat-row gathers are in flight per iteration.
// ---------------------------------------------------------------------------
__global__ void aggregate_kernel(const void* __restrict__ src,
                                 float* __restrict__ aout,
                                 float* __restrict__ rst, int E, int N)
{
    int n    = (int)((blockIdx.x * (size_t)blockDim.x + threadIdx.x) >> 5);
    int lane = threadIdx.x & 31;
    if (n >= N) return;
    int is64  = g_is64;
    int start = g_off[n];
    int cnt   = g_cnt[n];
    if (cnt == 0) return;

    float su = 1.f;
    if (lane < HEADS) su = fmaxf(g_esum[n * HEADS + lane], 1e-20f);

    float4 accA = make_float4(0.f, 0.f, 0.f, 0.f);
    float4 accB = make_float4(0.f, 0.f, 0.f, 0.f);
    int hA = lane >> 4;
    int hB = 2 + hA;

    int j = 0;
    for (; j + 2 <= cnt; j += 2) {
        // indices for both edges first (independent chains)
        int e0 = g_csr[start + j];
        int e1 = g_csr[start + j + 1];
        int s0 = load_idx(src, e0, is64, N);
        int s1 = load_idx(src, e1, is64, N);
        float x0 = 0.f, x1 = 0.f;
        if (lane < HEADS) {
            x0 = aout[(size_t)e0 * HEADS + lane];
            x1 = aout[(size_t)e1 * HEADS + lane];
        }
        // issue all four row loads before any math
        const float4* f0 = (const float4*)(g_feat_src + (size_t)s0 * INF_DIM);
        const float4* f1 = (const float4*)(g_feat_src + (size_t)s1 * INF_DIM);
        float4 v0 = f0[lane];
        float4 w0 = f0[lane + 32];
        float4 v1 = f1[lane];
        float4 w1 = f1[lane + 32];

        float a0 = 0.f, a1 = 0.f;
        if (lane < HEADS) {
            a0 = x0 / su;
            a1 = x1 / su;
            aout[(size_t)e0 * HEADS + lane] = a0;
            aout[(size_t)e1 * HEADS + lane] = a1;
        }
        float aA0 = __shfl_sync(0xffffffffu, a0, hA);
        float aB0 = __shfl_sync(0xffffffffu, a0, hB);
        float aA1 = __shfl_sync(0xffffffffu, a1, hA);
        float aB1 = __shfl_sync(0xffffffffu, a1, hB);

        accA.x += v0.x * aA0; accA.y += v0.y * aA0; accA.z += v0.z * aA0; accA.w += v0.w * aA0;
        accB.x += w0.x * aB0; accB.y += w0.y * aB0; accB.z += w0.z * aB0; accB.w += w0.w * aB0;
        accA.x += v1.x * aA1; accA.y += v1.y * aA1; accA.z += v1.z * aA1; accA.w += v1.w * aA1;
        accB.x += w1.x * aB1; accB.y += w1.y * aB1; accB.z += w1.z * aB1; accB.w += w1.w * aB1;
    }
    if (j < cnt) {
        int e = g_csr[start + j];
        int s = load_idx(src, e, is64, N);
        float av = 0.f;
        if (lane < HEADS) {
            av = aout[(size_t)e * HEADS + lane] / su;
            aout[(size_t)e * HEADS + lane] = av;
        }
        float aA = __shfl_sync(0xffffffffu, av, hA);
        float aB = __shfl_sync(0xffffffffu, av, hB);
        const float4* fs4 = (const float4*)(g_feat_src + (size_t)s * INF_DIM);
        float4 v = fs4[lane];
        float4 w = fs4[lane + 32];
        accA.x += v.x * aA; accA.y += v.y * aA; accA.z += v.z * aA; accA.w += v.w * aA;
        accB.x += w.x * aB; accB.y += w.y * aB; accB.z += w.z * aB; accB.w += w.w * aB;
    }

    float4* r4 = (float4*)(rst + (size_t)n * INF_DIM);
    float4 r = r4[lane];
    r.x += accA.x; r.y += accA.y; r.z += accA.z; r.w += accA.w;
    r4[lane] = r;
    float4 q = r4[lane + 32];
    q.x += accB.x; q.y += accB.y; q.z += accB.z; q.w += accB.w;
    r4[lane + 32] = q;
}

extern "C" void kernel_launch(void* const* d_in, const int* in_sizes, int n_in,
                              void* d_out, int out_size)
{
    const float* feat   = (const float*)d_in[0];
    const void*  src    = d_in[1];
    const void*  dst    = d_in[2];
    const float* Wfc    = (const float*)d_in[3];
    const float* attn_l = (const float*)d_in[4];
    const float* attn_r = (const float*)d_in[5];
    const float* Wres   = (const float*)d_in[6];
    const float* bias   = (const float*)d_in[7];

    const int N = in_sizes[0] / INF_DIM;
    const int E = in_sizes[1];

    float* rst = (float*)d_out;
    float* aout;
    if ((long long)out_size >= (long long)N * INF_DIM + (long long)E * HEADS) {
        aout = rst + (size_t)N * INF_DIM;
    } else {
        void* p = nullptr;
        cudaGetSymbolAddress(&p, g_ex);
        aout = (float*)p;
    }

    const int nb = (N + 1023) / 1024;
    const bool overlap = (g_s1 != nullptr) && (g_evFork != nullptr) && (g_evJoin != nullptr);
    cudaStream_t sb = overlap ? g_s1 : (cudaStream_t)0;

    // 0) index dtype probe
    detect_kernel<<<1, 32>>>((const int*)src);

    if (overlap) {
        cudaEventRecord(g_evFork, (cudaStream_t)0);
        cudaStreamWaitEvent(g_s1, g_evFork, 0);
    }

    // --- side stream: CSR-by-dst build (independent of GEMM) ---
    zerocnt_kernel<<<(N + 255) / 256, 256, 0, sb>>>(N);
    hist_kernel<<<(E + 255) / 256, 256, 0, sb>>>(dst, E, N);
    scan1_kernel<<<nb, 1024, 0, sb>>>(N);
    scan2_kernel<<<1, 128, 0, sb>>>(nb);
    scan3_kernel<<<nb, 1024, 0, sb>>>(N);
    scatter_kernel<<<(E + 255) / 256, 256, 0, sb>>>(dst, E, N);
    if (overlap) cudaEventRecord(g_evJoin, g_s1);

    // --- main stream: pre-convert + esum zero -> GEMM(+fused elr) -> edges ---
    convB_kernel<<<128, 256>>>(Wfc, Wres);
    zeroesum_kernel<<<(N * HEADS + 255) / 256, 256>>>(N * HEADS);
    dim3 ggrid(2, (N + 63) / 64);
    gemm_kernel<<<ggrid, 256>>>(feat, bias, attn_l, attn_r, rst, N);
    edge_kernel<<<(E + 255) / 256, 256>>>(src, dst, aout, E, N);

    if (overlap) cudaStreamWaitEvent((cudaStream_t)0, g_evJoin, 0);

    // --- chained pull aggregation (2-way unrolled) ---
    aggregate_kernel<<<(N + 7) / 8, 256>>>(src, aout, rst, E, N);
}